// round 17
// baseline (speedup 1.0000x reference)
#include <cuda_runtime.h>
#include <math.h>
#include <stdint.h>

#define MAXN 50048
#define MAXE 1650080

// ------------ static device scratch (zero-initialized at load) -----------
__device__ float d_h1[MAXN * 64];
__device__ float d_as1[MAXN * 8];
__device__ float d_ad1[MAXN * 8];
__device__ float d_x1[MAXN * 64];
__device__ float d_z[MAXN * 64];
__device__ float d_as2[MAXN];
__device__ float d_ad2[MAXN];
__device__ float d_wsrc[64];
__device__ float d_wdst[64];
__device__ int   d_deg[MAXN];      // zero at load; k_scan re-zeroes after use
__device__ int   d_off[MAXN + 1];
__device__ int   d_cur[MAXN];
__device__ int   d_ssrc[MAXE];

// ---------------- hist (+ block0 computes wsrc/wdst = W2 @ att2) ----------
__global__ void k_hist(const int* __restrict__ ei, int E, int vec,
                       const float* __restrict__ W2,
                       const float* __restrict__ as2v, const float* __restrict__ ad2v) {
    if (blockIdx.x == 0 && threadIdx.x < 128) {
        int k = threadIdx.x & 63;
        const float* att = (threadIdx.x < 64) ? as2v : ad2v;
        float s = 0.f;
#pragma unroll 16
        for (int c = 0; c < 128; c++) s += W2[k * 128 + c] * att[c];
        if (threadIdx.x < 64) d_wsrc[k] = s;
        else                  d_wdst[k] = s;
    }
    int i = blockIdx.x * blockDim.x + threadIdx.x;
    int e = i * 4;
    if (e >= E) return;
    if (vec && e + 3 < E) {
        int4 d = *(const int4*)(ei + E + e);
        atomicAdd(&d_deg[d.x], 1);
        atomicAdd(&d_deg[d.y], 1);
        atomicAdd(&d_deg[d.z], 1);
        atomicAdd(&d_deg[d.w], 1);
    } else {
        for (int j = e; j < E && j < e + 4; j++)
            atomicAdd(&d_deg[ei[E + j]], 1);
    }
}

// single-block scan; places self loop at slot 0; re-zeroes d_deg
__global__ __launch_bounds__(1024) void k_scan(int n) {
    __shared__ int warpsum[32];
    int t = threadIdx.x, lane = t & 31, wid = t >> 5;
    int ipt = (n + 1023) >> 10;
    int start = t * ipt;
    int endi  = min(start + ipt, n);
    int s = 0;
    for (int i = start; i < endi; i++) s += d_deg[i] + 1;
    int incl = s;
#pragma unroll
    for (int o = 1; o < 32; o <<= 1) {
        int v = __shfl_up_sync(0xffffffffu, incl, o);
        if (lane >= o) incl += v;
    }
    if (lane == 31) warpsum[wid] = incl;
    __syncthreads();
    if (wid == 0) {
        int v = warpsum[lane];
        int wi = v;
#pragma unroll
        for (int o = 1; o < 32; o <<= 1) {
            int u = __shfl_up_sync(0xffffffffu, wi, o);
            if (lane >= o) wi += u;
        }
        warpsum[lane] = wi - v;
    }
    __syncthreads();
    int run = warpsum[wid] + (incl - s);
    for (int i = start; i < endi; i++) {
        int d = d_deg[i];
        d_deg[i] = 0;
        d_off[i]  = run;
        d_ssrc[run] = i;
        d_cur[i]  = run + 1;
        run += d + 1;
    }
    if (t == 1023) d_off[n] = run;
}

// ------------- Fused Layer-1 GEMM + scatter (interleaved roles) -----------
__global__ __launch_bounds__(256) void k_gemm1_scatter(
    const float* __restrict__ x, const float* __restrict__ W1,
    const float* __restrict__ as, const float* __restrict__ ad, int n,
    const int* __restrict__ ei, int E, int vec)
{
    __shared__ float2 Ws[128 * 32];
    __shared__ float atts[64], attd[64];
    int t = threadIdx.x;

    if (blockIdx.x & 1) {
        int i = (blockIdx.x >> 1) * blockDim.x + t;
        int e = i * 4;
        if (e >= E) return;
        if (vec && e + 3 < E) {
            int4 s = *(const int4*)(ei + e);
            int4 d = *(const int4*)(ei + E + e);
            d_ssrc[atomicAdd(&d_cur[d.x], 1)] = s.x;
            d_ssrc[atomicAdd(&d_cur[d.y], 1)] = s.y;
            d_ssrc[atomicAdd(&d_cur[d.z], 1)] = s.z;
            d_ssrc[atomicAdd(&d_cur[d.w], 1)] = s.w;
        } else {
            for (int j = e; j < E && j < e + 4; j++)
                d_ssrc[atomicAdd(&d_cur[ei[E + j]], 1)] = ei[j];
        }
        return;
    }

    int w = t >> 5, l = t & 31;
    int nblk = gridDim.x >> 1;
    int bid  = blockIdx.x >> 1;
    const float2* Wv = (const float2*)W1;
    for (int i = t; i < 4096; i += 256) Ws[i] = Wv[i];
    if (t < 64) { atts[t] = as[t]; attd[t] = ad[t]; }
    __syncthreads();
    int ntiles = (n + 3) >> 2;
    for (int tile = bid * 8 + w; tile < ntiles; tile += nblk * 8) {
        int row0 = tile * 4;
        float xr[4][4];
#pragma unroll
        for (int r = 0; r < 4; r++) {
            const float* xp = x + (size_t)min(row0 + r, n - 1) * 128;
#pragma unroll
            for (int c = 0; c < 4; c++) xr[r][c] = xp[l + 32 * c];
        }
        float2 acc[4] = {{0,0},{0,0},{0,0},{0,0}};
#pragma unroll
        for (int c = 0; c < 4; c++) {
#pragma unroll 8
            for (int kk = 0; kk < 32; kk++) {
                float2 wv = Ws[(c * 32 + kk) * 32 + l];
#pragma unroll
                for (int r = 0; r < 4; r++) {
                    float xv = __shfl_sync(0xffffffffu, xr[r][c], kk);
                    acc[r].x += xv * wv.x;
                    acc[r].y += xv * wv.y;
                }
            }
        }
#pragma unroll
        for (int r = 0; r < 4; r++) {
            int row = row0 + r;
            if (row >= n) break;
            ((float2*)(d_h1 + (size_t)row * 64))[l] = acc[r];
            float ps = acc[r].x * atts[2 * l] + acc[r].y * atts[2 * l + 1];
            float pd = acc[r].x * attd[2 * l] + acc[r].y * attd[2 * l + 1];
            ps += __shfl_xor_sync(0xffffffffu, ps, 1);
            ps += __shfl_xor_sync(0xffffffffu, ps, 2);
            pd += __shfl_xor_sync(0xffffffffu, pd, 1);
            pd += __shfl_xor_sync(0xffffffffu, pd, 2);
            if ((l & 3) == 0) {
                d_as1[row * 8 + (l >> 2)] = ps;
                d_ad1[row * 8 + (l >> 2)] = pd;
            }
        }
    }
}

// --------------------------- Layer 1 aggregate ---------------------------
// Persistent warps + node-level software pipelining: next node's off/adv
// prefetched at loop top (overlaps current gathers), next idx before the
// epilogue; within-node chunk idx prefetched one chunk ahead.
__global__ __launch_bounds__(256) void k_agg1(const float* __restrict__ bias1, int n) {
    int t = threadIdx.x, w = t >> 5, l = t & 31;
    int hl = l >> 2;
    int gw = blockIdx.x * 8 + w;
    int nw = gridDim.x * 8;
    if (gw >= n) return;
    int node = gw;
    int beg = d_off[node], end = d_off[node + 1];
    float adv = d_ad1[node * 8 + (l & 7)];
    int idx = d_ssrc[min(beg + l, end - 1)];
    while (true) {
        int nnode = node + nw;
        bool hn = nnode < n;
        int nbeg = 0, nend = 1;
        float nadv = 0.f;
        if (hn) {
            nbeg = d_off[nnode];
            nend = d_off[nnode + 1];
            nadv = d_ad1[nnode * 8 + (l & 7)];
        }
        float acc0 = 0.f, acc1 = 0.f, dloc = 0.f;
        for (int ch = beg; ch < end; ch += 32) {
            int cnt = end - ch;
            int idxn = 0;
            if (ch + 32 < end) idxn = d_ssrc[min(ch + 32 + l, end - 1)];
            float ec[8];
#pragma unroll
            for (int g = 0; g < 8; g++) {
                int ka = g * 4 + (l >> 3);
                int sA = __shfl_sync(0xffffffffu, idx, g * 4 + (l >> 3));
                float e = 0.f;
                if (ka < cnt) {
                    float al = __ldg(&d_as1[sA * 8 + (l & 7)]) + adv;
                    al = (al >= 0.f) ? al : 0.2f * al;
                    e = __expf(al);
                }
                ec[g] = e;
                dloc += e;
            }
#pragma unroll
            for (int g8 = 0; g8 < 4; g8++) {
                if (g8 * 8 >= cnt) break;
                int sj[8];
#pragma unroll
                for (int j = 0; j < 8; j++)
                    sj[j] = __shfl_sync(0xffffffffu, idx, g8 * 8 + j);
                float2 hj[8];
#pragma unroll
                for (int j = 0; j < 8; j++)
                    hj[j] = ((const float2*)(d_h1 + (size_t)sj[j] * 64))[l];
                float ev[8];
#pragma unroll
                for (int j = 0; j < 8; j++)
                    ev[j] = __shfl_sync(0xffffffffu, ec[g8 * 2 + (j >> 2)], (j & 3) * 8 + hl);
#pragma unroll
                for (int j = 0; j < 8; j++) {
                    acc0 += ev[j] * hj[j].x;
                    acc1 += ev[j] * hj[j].y;
                }
            }
            idx = idxn;
        }
        int nidx = 0;
        if (hn) nidx = d_ssrc[min(nbeg + l, nend - 1)];
        dloc += __shfl_xor_sync(0xffffffffu, dloc, 8);
        dloc += __shfl_xor_sync(0xffffffffu, dloc, 16);
        float dsum = __shfl_sync(0xffffffffu, dloc, hl);
        float inv = 1.f / (dsum + 1e-16f);
        float o0 = acc0 * inv + bias1[2 * l];
        float o1 = acc1 * inv + bias1[2 * l + 1];
        o0 = (o0 > 0.f) ? o0 : expm1f(o0);
        o1 = (o1 > 0.f) ? o1 : expm1f(o1);
        ((float2*)(d_x1 + (size_t)node * 64))[l] = make_float2(o0, o1);
        float ss = o0 * d_wsrc[2 * l] + o1 * d_wsrc[2 * l + 1];
        float sd = o0 * d_wdst[2 * l] + o1 * d_wdst[2 * l + 1];
#pragma unroll
        for (int o = 16; o; o >>= 1) {
            ss += __shfl_xor_sync(0xffffffffu, ss, o);
            sd += __shfl_xor_sync(0xffffffffu, sd, o);
        }
        if (l == 0) { d_as2[node] = ss; d_ad2[node] = sd; }
        if (!hn) break;
        node = nnode; beg = nbeg; end = nend; adv = nadv; idx = nidx;
    }
}

// --------------------------- Layer 2 aggregate ---------------------------
// Persistent + node-level pipelining. Critical extra: the per-lane scattered
// as2 load (32 divergent 4B addresses, whole chunk's e depends on it) is
// prefetched one chunk / one node ahead, hiding its full L2 latency chain.
__global__ __launch_bounds__(256) void k_agg2(int n) {
    int t = threadIdx.x, w = t >> 5, l = t & 31;
    int gw = blockIdx.x * 8 + w;
    int nw = gridDim.x * 8;
    if (gw >= n) return;
    int node = gw;
    int beg = d_off[node], end = d_off[node + 1];
    float adv = d_ad2[node];
    int idx = d_ssrc[min(beg + l, end - 1)];
    float a2 = __ldg(&d_as2[idx]);
    while (true) {
        int nnode = node + nw;
        bool hn = nnode < n;
        int nbeg = 0, nend = 1;
        float nadv = 0.f;
        if (hn) {
            nbeg = d_off[nnode];
            nend = d_off[nnode + 1];
            nadv = d_ad2[nnode];
        }
        float x0 = 0.f, x1v = 0.f, dpart = 0.f;
        for (int ch = beg; ch < end; ch += 32) {
            int cnt = end - ch;
            int idxn = 0;
            float a2n = 0.f;
            if (ch + 32 < end) {
                idxn = d_ssrc[min(ch + 32 + l, end - 1)];
                a2n = __ldg(&d_as2[idxn]);
            }
            float e = 0.f;
            if (l < cnt) {
                float al = a2 + adv;
                al = (al >= 0.f) ? al : 0.2f * al;
                e = __expf(al);
                dpart += e;
            }
#pragma unroll
            for (int g8 = 0; g8 < 4; g8++) {
                if (g8 * 8 >= cnt) break;
                int sj[8];
                float ej[8];
#pragma unroll
                for (int j = 0; j < 8; j++) {
                    sj[j] = __shfl_sync(0xffffffffu, idx, g8 * 8 + j);
                    ej[j] = __shfl_sync(0xffffffffu, e,   g8 * 8 + j);
                }
                float2 hj[8];
#pragma unroll
                for (int j = 0; j < 8; j++)
                    hj[j] = ((const float2*)(d_x1 + (size_t)sj[j] * 64))[l];
#pragma unroll
                for (int j = 0; j < 8; j++) {
                    x0  += ej[j] * hj[j].x;
                    x1v += ej[j] * hj[j].y;
                }
            }
            idx = idxn;
            a2 = a2n;
        }
        int nidx = 0;
        float na2 = 0.f;
        if (hn) {
            nidx = d_ssrc[min(nbeg + l, nend - 1)];
            na2 = __ldg(&d_as2[nidx]);
        }
#pragma unroll
        for (int o = 16; o; o >>= 1) dpart += __shfl_xor_sync(0xffffffffu, dpart, o);
        float inv = 1.f / (dpart + 1e-16f);
        ((float2*)(d_z + (size_t)node * 64))[l] = make_float2(x0 * inv, x1v * inv);
        if (!hn) break;
        node = nnode; beg = nbeg; end = nend; adv = nadv; idx = nidx; a2 = na2;
    }
}

// ---------------------- Final GEMM: out = z @ W2 + b2 --------------------
__global__ __launch_bounds__(256) void k_gemmF(
    const float* __restrict__ W2, const float* __restrict__ bias2,
    float* __restrict__ out, int n)
{
    __shared__ float4 Ws[64 * 32];
    __shared__ float4 bs[32];
    int t = threadIdx.x, w = t >> 5, l = t & 31;
    const float4* Wv = (const float4*)W2;
    for (int i = t; i < 2048; i += 256) Ws[i] = Wv[i];
    if (t < 32) bs[t] = ((const float4*)bias2)[t];
    __syncthreads();
    int ntiles = (n + 3) >> 2;
    for (int tile = blockIdx.x * 8 + w; tile < ntiles; tile += gridDim.x * 8) {
        int row0 = tile * 4;
        float xr[4][2];
#pragma unroll
        for (int r = 0; r < 4; r++) {
            const float* xp = d_z + (size_t)min(row0 + r, n - 1) * 64;
#pragma unroll
            for (int c = 0; c < 2; c++) xr[r][c] = xp[l + 32 * c];
        }
        float4 acc[4] = {{0,0,0,0},{0,0,0,0},{0,0,0,0},{0,0,0,0}};
#pragma unroll
        for (int c = 0; c < 2; c++) {
#pragma unroll 8
            for (int kk = 0; kk < 32; kk++) {
                float4 wv = Ws[(c * 32 + kk) * 32 + l];
#pragma unroll
                for (int r = 0; r < 4; r++) {
                    float xv = __shfl_sync(0xffffffffu, xr[r][c], kk);
                    acc[r].x += xv * wv.x; acc[r].y += xv * wv.y;
                    acc[r].z += xv * wv.z; acc[r].w += xv * wv.w;
                }
            }
        }
        float4 b = bs[l];
#pragma unroll
        for (int r = 0; r < 4; r++) {
            int row = row0 + r;
            if (row >= n) break;
            ((float4*)(out + (size_t)row * 128))[l] =
                make_float4(acc[r].x + b.x, acc[r].y + b.y,
                            acc[r].z + b.z, acc[r].w + b.w);
        }
    }
}

// ------------------------------- launch ----------------------------------
extern "C" void kernel_launch(void* const* d_in, const int* in_sizes, int n_in,
                              void* d_out, int out_size)
{
    const float* x    = (const float*)d_in[0];
    const int*   ei   = (const int*)d_in[1];
    const float* W1   = (const float*)d_in[2];
    const float* asr1 = (const float*)d_in[3];
    const float* ads1 = (const float*)d_in[4];
    const float* b1   = (const float*)d_in[5];
    const float* W2   = (const float*)d_in[6];
    const float* asr2 = (const float*)d_in[7];
    const float* ads2 = (const float*)d_in[8];
    const float* b2   = (const float*)d_in[9];
    float* out = (float*)d_out;

    int N  = in_sizes[0] / 128;
    int E  = in_sizes[1] / 2;
    int vec = ((E & 3) == 0) ? 1 : 0;
    int e4 = (E + 3) / 4;

    k_hist<<<(e4 + 255) / 256, 256>>>(ei, E, vec, W2, asr2, ads2);
    k_scan<<<1, 1024>>>(N);

    int ntb = ((N + 3) / 4 + 7) / 8;
    int sb  = (e4 + 255) / 256;
    int G   = 2 * (ntb > sb ? ntb : sb);
    k_gemm1_scatter<<<G, 256>>>(x, W1, asr1, ads1, N, ei, E, vec);

    k_agg1<<<1184, 256>>>(b1, N);
    k_agg2<<<1184, 256>>>(N);
    k_gemmF<<<ntb, 256>>>(W2, b2, out, N);
}